// round 1
// baseline (speedup 1.0000x reference)
#include <cuda_runtime.h>
#include <cuda_bf16.h>

#define N_NODES 8192
#define F_INP   512
#define H_DIM   256
#define D_DIM   64
#define N_EDGES 262144

// Scratch (device globals: no allocation allowed in kernel_launch)
__device__ float g_hpre[N_NODES * H_DIM];  // x@W1 + b1
__device__ float g_h   [N_NODES * H_DIM];  // spmm1 accumulator (relu applied on read)
__device__ float g_zpre[N_NODES * D_DIM];  // relu(h)@W2 + b2
__device__ float g_z   [N_NODES * D_DIM];  // spmm2 accumulator = z

// ---------------------------------------------------------------------------
// Zero the two scatter accumulators (d_out is poisoned; accumulators persist
// across graph replays so they must be re-zeroed every call).
// ---------------------------------------------------------------------------
__global__ void zero_accum_kernel() {
    int i = blockIdx.x * blockDim.x + threadIdx.x;
    if (i < N_NODES * H_DIM) g_h[i] = 0.0f;
    if (i < N_NODES * D_DIM) g_z[i] = 0.0f;
}

// ---------------------------------------------------------------------------
// Tiled fp32 GEMM:  C[M,Nc] = op(A[M,K]) @ B[K,Nc] + bias[Nc]
// BM=64, BN=64, BK=16, 256 threads, 4x4 per thread.
// Smem staged transposed ([k][row]) so the inner loop reads are conflict-light.
// ---------------------------------------------------------------------------
template <bool RELU_A>
__global__ void gemm_bias_kernel(const float* __restrict__ A,
                                 const float* __restrict__ B,
                                 const float* __restrict__ bias,
                                 float* __restrict__ C,
                                 int M, int Nc, int K) {
    constexpr int BM = 64, BN = 64, BK = 16, TM = 4, TN = 4;
    __shared__ float As[BK][BM + 4];
    __shared__ float Bs[BK][BN + 4];

    const int row0 = blockIdx.y * BM;
    const int col0 = blockIdx.x * BN;
    const int tid  = threadIdx.x;
    const int tx   = tid % (BN / TN);   // 0..15
    const int ty   = tid / (BN / TN);   // 0..15

    float acc[TM][TN] = {};

    for (int k0 = 0; k0 < K; k0 += BK) {
        // Stage A tile transposed: As[k][r]
        #pragma unroll
        for (int t = tid; t < BM * BK; t += 256) {
            int r  = t / BK;
            int kk = t % BK;
            float v = __ldg(&A[(size_t)(row0 + r) * K + k0 + kk]);
            if (RELU_A) v = fmaxf(v, 0.0f);
            As[kk][r] = v;
        }
        // Stage B tile: Bs[k][c]  (coalesced gmem read)
        #pragma unroll
        for (int t = tid; t < BK * BN; t += 256) {
            int kk = t / BN;
            int c  = t % BN;
            Bs[kk][c] = __ldg(&B[(size_t)(k0 + kk) * Nc + col0 + c]);
        }
        __syncthreads();

        #pragma unroll
        for (int kk = 0; kk < BK; kk++) {
            float a[TM], b[TN];
            #pragma unroll
            for (int i = 0; i < TM; i++) a[i] = As[kk][ty * TM + i];
            #pragma unroll
            for (int j = 0; j < TN; j++) b[j] = Bs[kk][tx * TN + j];
            #pragma unroll
            for (int i = 0; i < TM; i++)
                #pragma unroll
                for (int j = 0; j < TN; j++)
                    acc[i][j] = fmaf(a[i], b[j], acc[i][j]);
        }
        __syncthreads();
    }

    #pragma unroll
    for (int i = 0; i < TM; i++) {
        int r = row0 + ty * TM + i;
        #pragma unroll
        for (int j = 0; j < TN; j++) {
            int c = col0 + tx * TN + j;
            C[(size_t)r * Nc + c] = acc[i][j] + bias[c];
        }
    }
}

// ---------------------------------------------------------------------------
// COO SpMM: out[rows[e], :] += vals[e] * in[cols[e], :]
// One warp per edge; lanes stride the feature dim (coalesced loads, and the
// atomicAdd targets are consecutive addresses -> spread across L2 slices).
// ---------------------------------------------------------------------------
template <int F>
__global__ void spmm_kernel(const int* __restrict__ rows,
                            const int* __restrict__ cols,
                            const float* __restrict__ vals,
                            const float* __restrict__ in,
                            float* __restrict__ out) {
    int warp = (blockIdx.x * blockDim.x + threadIdx.x) >> 5;
    int lane = threadIdx.x & 31;
    if (warp >= N_EDGES) return;
    int   r = __ldg(&rows[warp]);
    int   c = __ldg(&cols[warp]);
    float v = __ldg(&vals[warp]);
    const float* src = in  + (size_t)c * F;
    float*       dst = out + (size_t)r * F;
    #pragma unroll
    for (int f = lane; f < F; f += 32)
        atomicAdd(&dst[f], v * __ldg(&src[f]));
}

// ---------------------------------------------------------------------------
// Copy z into the first N*D elements of the output.
// ---------------------------------------------------------------------------
__global__ void copy_z_kernel(const float* __restrict__ z, float* __restrict__ out) {
    int i = blockIdx.x * blockDim.x + threadIdx.x;
    if (i < N_NODES * D_DIM) out[i] = z[i];
}

// ---------------------------------------------------------------------------
// Decoder: adj_rec[i,j] = sigmoid(dot(z[i,:], z[j,:])), K = 64.
// 64x64 tile per block, z tiles staged transposed in smem ([k][row]).
// ---------------------------------------------------------------------------
__global__ void decode_kernel(const float* __restrict__ z, float* __restrict__ out) {
    __shared__ float zi[D_DIM][64 + 4];
    __shared__ float zj[D_DIM][64 + 4];

    const int i0  = blockIdx.y * 64;
    const int j0  = blockIdx.x * 64;
    const int tid = threadIdx.x;

    #pragma unroll
    for (int t = tid; t < 64 * D_DIM; t += 256) {
        int r = t >> 6;        // row within tile
        int k = t & 63;        // feature
        zi[k][r] = __ldg(&z[(size_t)(i0 + r) * D_DIM + k]);
        zj[k][r] = __ldg(&z[(size_t)(j0 + r) * D_DIM + k]);
    }
    __syncthreads();

    const int tx = tid % 16;
    const int ty = tid / 16;
    float acc[4][4] = {};

    #pragma unroll
    for (int k = 0; k < D_DIM; k++) {
        float a[4], b[4];
        #pragma unroll
        for (int i = 0; i < 4; i++) a[i] = zi[k][ty * 4 + i];
        #pragma unroll
        for (int j = 0; j < 4; j++) b[j] = zj[k][tx * 4 + j];
        #pragma unroll
        for (int i = 0; i < 4; i++)
            #pragma unroll
            for (int j = 0; j < 4; j++)
                acc[i][j] = fmaf(a[i], b[j], acc[i][j]);
    }

    #pragma unroll
    for (int i = 0; i < 4; i++) {
        size_t r = (size_t)(i0 + ty * 4 + i);
        #pragma unroll
        for (int j = 0; j < 4; j++) {
            int c = j0 + tx * 4 + j;
            float s = acc[i][j];
            out[r * N_NODES + c] = 1.0f / (1.0f + __expf(-s));
        }
    }
}

// ---------------------------------------------------------------------------
extern "C" void kernel_launch(void* const* d_in, const int* in_sizes, int n_in,
                              void* d_out, int out_size) {
    const float* x    = (const float*)d_in[0];
    const int*   rows = (const int*)  d_in[1];
    const int*   cols = (const int*)  d_in[2];
    const float* vals = (const float*)d_in[3];
    const float* W1   = (const float*)d_in[4];
    const float* b1   = (const float*)d_in[5];
    const float* W2   = (const float*)d_in[6];
    const float* b2   = (const float*)d_in[7];
    float* out = (float*)d_out;

    float *hpre, *h, *zpre, *z;
    cudaGetSymbolAddress((void**)&hpre, g_hpre);
    cudaGetSymbolAddress((void**)&h,    g_h);
    cudaGetSymbolAddress((void**)&zpre, g_zpre);
    cudaGetSymbolAddress((void**)&z,    g_z);

    // 0. zero scatter accumulators
    {
        int n = N_NODES * H_DIM;
        zero_accum_kernel<<<(n + 255) / 256, 256>>>();
    }

    // 1. hpre = x @ W1 + b1       [8192, 256]
    {
        dim3 grid(H_DIM / 64, N_NODES / 64);
        gemm_bias_kernel<false><<<grid, 256>>>(x, W1, b1, hpre, N_NODES, H_DIM, F_INP);
    }

    // 2. h = spmm(hpre)           [8192, 256]
    {
        int warps_per_block = 8;
        int blocks = N_EDGES / warps_per_block;
        spmm_kernel<H_DIM><<<blocks, warps_per_block * 32>>>(rows, cols, vals, hpre, h);
    }

    // 3. zpre = relu(h) @ W2 + b2 [8192, 64]
    {
        dim3 grid(D_DIM / 64, N_NODES / 64);
        gemm_bias_kernel<true><<<grid, 256>>>(h, W2, b2, zpre, N_NODES, D_DIM, H_DIM);
    }

    // 4. z = spmm(zpre)           [8192, 64]
    {
        int warps_per_block = 8;
        int blocks = N_EDGES / warps_per_block;
        spmm_kernel<D_DIM><<<blocks, warps_per_block * 32>>>(rows, cols, vals, zpre, z);
    }

    // 5. out[0 : N*D] = z
    {
        int n = N_NODES * D_DIM;
        copy_z_kernel<<<(n + 255) / 256, 256>>>(z, out);
    }

    // 6. out[N*D : ] = sigmoid(z @ z^T)   [8192, 8192]
    {
        dim3 grid(N_NODES / 64, N_NODES / 64);
        decode_kernel<<<grid, 256>>>(z, out + (size_t)N_NODES * D_DIM);
    }
}

// round 2
// speedup vs baseline: 1.1135x; 1.1135x over previous
#include <cuda_runtime.h>
#include <cuda_bf16.h>

#define N_NODES 8192
#define F_INP   512
#define H_DIM   256
#define D_DIM   64
#define N_EDGES 262144

// ---------------- device scratch (no allocation allowed) --------------------
__device__ float g_hpre[N_NODES * H_DIM];   // x@W1 + b1
__device__ float g_h   [N_NODES * H_DIM];   // spmm1 out
__device__ float g_zpre[N_NODES * D_DIM];   // relu(h)@W2 + b2
__device__ int   g_cnt   [N_NODES];         // per-row edge count
__device__ int   g_rowptr[N_NODES + 1];     // CSR row pointers
__device__ int   g_fill  [N_NODES];         // scatter cursors
__device__ int   g_ecol  [N_EDGES];         // cols sorted by row
__device__ float g_eval  [N_EDGES];         // vals sorted by row

// ---------------- packed f32x2 FMA (FFMA2: 2x fp32 rate on sm_103a) --------
__device__ __forceinline__ float2 ffma2(float2 a, float2 b, float2 c) {
    union U { float2 f; unsigned long long u; };
    U A, B, C;
    A.f = a; B.f = b; C.f = c;
    asm("fma.rn.f32x2 %0, %1, %2, %0;" : "+l"(C.u) : "l"(A.u), "l"(B.u));
    return C.f;
}

// ============================ CSR build =====================================
__global__ void zero_cnt_kernel() {
    int i = blockIdx.x * blockDim.x + threadIdx.x;
    if (i < N_NODES) g_cnt[i] = 0;
}

__global__ void count_kernel(const int* __restrict__ rows) {
    int e = blockIdx.x * blockDim.x + threadIdx.x;
    if (e < N_EDGES) atomicAdd(&g_cnt[rows[e]], 1);
}

// single block, 1024 threads, 8 elements each -> exclusive scan of 8192
__global__ void scan_kernel() {
    __shared__ int sm[1024];
    int tid  = threadIdx.x;
    int base = tid * 8;
    int v[8], pre[8];
    int s = 0;
    #pragma unroll
    for (int i = 0; i < 8; i++) { v[i] = g_cnt[base + i]; pre[i] = s; s += v[i]; }
    sm[tid] = s;
    __syncthreads();
    // Hillis-Steele inclusive scan
    for (int off = 1; off < 1024; off <<= 1) {
        int t = (tid >= off) ? sm[tid - off] : 0;
        __syncthreads();
        sm[tid] += t;
        __syncthreads();
    }
    int excl = sm[tid] - s;     // exclusive offset for this thread's chunk
    #pragma unroll
    for (int i = 0; i < 8; i++) {
        int p = excl + pre[i];
        g_rowptr[base + i] = p;
        g_fill[base + i]   = p;
    }
    if (tid == 1023) g_rowptr[N_NODES] = sm[1023];
}

__global__ void scatter_kernel(const int* __restrict__ rows,
                               const int* __restrict__ cols,
                               const float* __restrict__ vals) {
    int e = blockIdx.x * blockDim.x + threadIdx.x;
    if (e >= N_EDGES) return;
    int pos = atomicAdd(&g_fill[rows[e]], 1);
    g_ecol[pos] = cols[e];
    g_eval[pos] = vals[e];
}

// ============================ GEMM (f32x2) ==================================
// C[M,Nc] = op(A) @ B + bias.  threads = (BM/TM)*(BN/TN) = 256.
template <int BM, int BN, int BK, int TM, int TN, bool RELU_A>
__global__ void __launch_bounds__(256)
gemm_f32x2_kernel(const float* __restrict__ A, const float* __restrict__ B,
                  const float* __restrict__ bias, float* __restrict__ C,
                  int M, int Nc, int K) {
    constexpr int SA = BM + 4;
    constexpr int SB = BN + 4;
    __shared__ float As[BK * SA];   // transposed: As[k][r]
    __shared__ float Bs[BK * SB];   // Bs[k][c]

    const int row0 = blockIdx.y * BM;
    const int col0 = blockIdx.x * BN;
    const int tid  = threadIdx.x;
    const int tx   = tid % (BN / TN);
    const int ty   = tid / (BN / TN);

    float2 acc[TM][TN / 2];
    #pragma unroll
    for (int i = 0; i < TM; i++)
        #pragma unroll
        for (int j = 0; j < TN / 2; j++) acc[i][j] = make_float2(0.f, 0.f);

    for (int k0 = 0; k0 < K; k0 += BK) {
        // stage A transposed (float4 gmem loads, scalar transposed STS)
        constexpr int AQ = BM * BK / 4;           // float4 count
        #pragma unroll
        for (int q = tid; q < AQ; q += 256) {
            int r  = q / (BK / 4);
            int kq = q % (BK / 4);
            float4 v = *(const float4*)&A[(size_t)(row0 + r) * K + k0 + kq * 4];
            if (RELU_A) {
                v.x = fmaxf(v.x, 0.f); v.y = fmaxf(v.y, 0.f);
                v.z = fmaxf(v.z, 0.f); v.w = fmaxf(v.w, 0.f);
            }
            As[(kq * 4 + 0) * SA + r] = v.x;
            As[(kq * 4 + 1) * SA + r] = v.y;
            As[(kq * 4 + 2) * SA + r] = v.z;
            As[(kq * 4 + 3) * SA + r] = v.w;
        }
        // stage B (float4 direct)
        constexpr int BQ = BK * BN / 4;
        #pragma unroll
        for (int q = tid; q < BQ; q += 256) {
            int k  = q / (BN / 4);
            int cq = q % (BN / 4);
            float4 v = *(const float4*)&B[(size_t)(k0 + k) * Nc + col0 + cq * 4];
            *(float4*)&Bs[k * SB + cq * 4] = v;
        }
        __syncthreads();

        #pragma unroll
        for (int kk = 0; kk < BK; kk++) {
            float a[TM];
            #pragma unroll
            for (int i = 0; i < TM; i += 4) {
                float4 av = *(const float4*)&As[kk * SA + ty * TM + i];
                a[i] = av.x; a[i + 1] = av.y; a[i + 2] = av.z; a[i + 3] = av.w;
            }
            float2 b[TN / 2];
            #pragma unroll
            for (int j = 0; j < TN; j += 4) {
                float4 bv = *(const float4*)&Bs[kk * SB + tx * TN + j];
                b[j / 2]     = make_float2(bv.x, bv.y);
                b[j / 2 + 1] = make_float2(bv.z, bv.w);
            }
            #pragma unroll
            for (int i = 0; i < TM; i++) {
                float2 av2 = make_float2(a[i], a[i]);
                #pragma unroll
                for (int j = 0; j < TN / 2; j++)
                    acc[i][j] = ffma2(av2, b[j], acc[i][j]);
            }
        }
        __syncthreads();
    }

    float bi_[TN];
    #pragma unroll
    for (int j = 0; j < TN; j++) bi_[j] = __ldg(&bias[col0 + tx * TN + j]);

    #pragma unroll
    for (int i = 0; i < TM; i++) {
        size_t row = (size_t)(row0 + ty * TM + i);
        #pragma unroll
        for (int j = 0; j < TN / 2; j++) {
            float2 o = make_float2(acc[i][j].x + bi_[j * 2],
                                   acc[i][j].y + bi_[j * 2 + 1]);
            *(float2*)&C[row * Nc + col0 + tx * TN + j * 2] = o;
        }
    }
}

// ============================ CSR SpMM ======================================
// one row handled by F threads; ROWS_PER_BLK rows per 256-thread block.
template <int F, int ROWS_PER_BLK>
__global__ void spmm_csr_kernel(const float* __restrict__ in,
                                float* __restrict__ out) {
    int sub = threadIdx.x / F;
    int f   = threadIdx.x % F;
    int row = blockIdx.x * ROWS_PER_BLK + sub;
    int s = g_rowptr[row];
    int e = g_rowptr[row + 1];
    float acc = 0.f;
    int j = s;
    for (; j + 4 <= e; j += 4) {
        int   c0 = g_ecol[j],     c1 = g_ecol[j + 1];
        int   c2 = g_ecol[j + 2], c3 = g_ecol[j + 3];
        float v0 = g_eval[j],     v1 = g_eval[j + 1];
        float v2 = g_eval[j + 2], v3 = g_eval[j + 3];
        float x0 = __ldg(&in[(size_t)c0 * F + f]);
        float x1 = __ldg(&in[(size_t)c1 * F + f]);
        float x2 = __ldg(&in[(size_t)c2 * F + f]);
        float x3 = __ldg(&in[(size_t)c3 * F + f]);
        acc = fmaf(v0, x0, acc); acc = fmaf(v1, x1, acc);
        acc = fmaf(v2, x2, acc); acc = fmaf(v3, x3, acc);
    }
    for (; j < e; j++)
        acc = fmaf(g_eval[j], __ldg(&in[(size_t)g_ecol[j] * F + f]), acc);
    out[(size_t)row * F + f] = acc;
}

// ============================ Decoder =======================================
// sigmoid(z z^T), symmetric: compute upper-triangle 128x128 tiles, mirror.
__global__ void __launch_bounds__(256)
decode_kernel(const float* __restrict__ z, float* __restrict__ out) {
    extern __shared__ float sm[];
    float* zi = sm;                 // [64][132] transposed
    float* zj = sm + 64 * 132;      // [64][132] transposed

    // linear block -> (bi, bj), bi <= bj, 64 tile-rows
    int t = blockIdx.x;
    int bi = 0, rem = t;
    while (rem >= 64 - bi) { rem -= 64 - bi; bi++; }
    int bj = bi + rem;
    const int i0 = bi * 128, j0 = bj * 128;
    const int tid = threadIdx.x;

    // stage z tiles transposed
    for (int q = tid; q < 128 * 16; q += 256) {
        int r = q >> 4, c4 = q & 15;
        float4 a = *(const float4*)&z[(size_t)(i0 + r) * 64 + c4 * 4];
        zi[(c4 * 4 + 0) * 132 + r] = a.x;
        zi[(c4 * 4 + 1) * 132 + r] = a.y;
        zi[(c4 * 4 + 2) * 132 + r] = a.z;
        zi[(c4 * 4 + 3) * 132 + r] = a.w;
        float4 b = *(const float4*)&z[(size_t)(j0 + r) * 64 + c4 * 4];
        zj[(c4 * 4 + 0) * 132 + r] = b.x;
        zj[(c4 * 4 + 1) * 132 + r] = b.y;
        zj[(c4 * 4 + 2) * 132 + r] = b.z;
        zj[(c4 * 4 + 3) * 132 + r] = b.w;
    }
    __syncthreads();

    const int tx = tid & 15, ty = tid >> 4;
    float2 acc[8][4];
    #pragma unroll
    for (int i = 0; i < 8; i++)
        #pragma unroll
        for (int j = 0; j < 4; j++) acc[i][j] = make_float2(0.f, 0.f);

    #pragma unroll 8
    for (int k = 0; k < 64; k++) {
        float4 a0 = *(const float4*)&zi[k * 132 + ty * 8];
        float4 a1 = *(const float4*)&zi[k * 132 + ty * 8 + 4];
        float4 b0 = *(const float4*)&zj[k * 132 + tx * 8];
        float4 b1 = *(const float4*)&zj[k * 132 + tx * 8 + 4];
        float  a[8] = {a0.x, a0.y, a0.z, a0.w, a1.x, a1.y, a1.z, a1.w};
        float2 b[4] = {make_float2(b0.x, b0.y), make_float2(b0.z, b0.w),
                       make_float2(b1.x, b1.y), make_float2(b1.z, b1.w)};
        #pragma unroll
        for (int i = 0; i < 8; i++) {
            float2 av = make_float2(a[i], a[i]);
            #pragma unroll
            for (int j = 0; j < 4; j++) acc[i][j] = ffma2(av, b[j], acc[i][j]);
        }
    }

    // direct tile write (i0, j0), coalesced float4
    #pragma unroll
    for (int i = 0; i < 8; i++) {
        size_t row = (size_t)(i0 + ty * 8 + i);
        float4 o0, o1;
        o0.x = 1.f / (1.f + __expf(-acc[i][0].x));
        o0.y = 1.f / (1.f + __expf(-acc[i][0].y));
        o0.z = 1.f / (1.f + __expf(-acc[i][1].x));
        o0.w = 1.f / (1.f + __expf(-acc[i][1].y));
        o1.x = 1.f / (1.f + __expf(-acc[i][2].x));
        o1.y = 1.f / (1.f + __expf(-acc[i][2].y));
        o1.z = 1.f / (1.f + __expf(-acc[i][3].x));
        o1.w = 1.f / (1.f + __expf(-acc[i][3].y));
        *(float4*)&out[row * N_NODES + j0 + tx * 8]     = o0;
        *(float4*)&out[row * N_NODES + j0 + tx * 8 + 4] = o1;
    }

    if (bi != bj) {
        // mirror write at (j0, i0): stage sigmoid tile, write transposed
        __syncthreads();                        // done reading zi/zj
        float* stg = sm;                        // [128][129]
        #pragma unroll
        for (int i = 0; i < 8; i++) {
            int r = ty * 8 + i;
            #pragma unroll
            for (int j = 0; j < 4; j++) {
                stg[r * 129 + tx * 8 + j * 2]     = 1.f / (1.f + __expf(-acc[i][j].x));
                stg[r * 129 + tx * 8 + j * 2 + 1] = 1.f / (1.f + __expf(-acc[i][j].y));
            }
        }
        __syncthreads();
        for (int idx = tid; idx < 128 * 128; idx += 256) {
            int c = idx >> 7;      // col of original tile -> row of mirror
            int r = idx & 127;     // row of original tile -> col of mirror
            out[(size_t)(j0 + c) * N_NODES + i0 + r] = stg[r * 129 + c];
        }
    }
}

// ============================ launch ========================================
extern "C" void kernel_launch(void* const* d_in, const int* in_sizes, int n_in,
                              void* d_out, int out_size) {
    const float* x    = (const float*)d_in[0];
    const int*   rows = (const int*)  d_in[1];
    const int*   cols = (const int*)  d_in[2];
    const float* vals = (const float*)d_in[3];
    const float* W1   = (const float*)d_in[4];
    const float* b1   = (const float*)d_in[5];
    const float* W2   = (const float*)d_in[6];
    const float* b2   = (const float*)d_in[7];
    float* out = (float*)d_out;

    float *hpre, *h, *zpre;
    cudaGetSymbolAddress((void**)&hpre, g_hpre);
    cudaGetSymbolAddress((void**)&h,    g_h);
    cudaGetSymbolAddress((void**)&zpre, g_zpre);

    // --- CSR build ---
    zero_cnt_kernel<<<N_NODES / 256, 256>>>();
    count_kernel<<<N_EDGES / 256, 256>>>(rows);
    scan_kernel<<<1, 1024>>>();
    scatter_kernel<<<N_EDGES / 256, 256>>>(rows, cols, vals);

    // --- layer 1: hpre = x @ W1 + b1  [8192,256], K=512 ---
    {
        dim3 grid(H_DIM / 128, N_NODES / 128);
        gemm_f32x2_kernel<128, 128, 16, 8, 8, false>
            <<<grid, 256>>>(x, W1, b1, hpre, N_NODES, H_DIM, F_INP);
    }
    // --- spmm1: h = A @ hpre  [8192,256] ---
    spmm_csr_kernel<H_DIM, 1><<<N_NODES, 256>>>(hpre, h);

    // --- layer 2: zpre = relu(h) @ W2 + b2  [8192,64], K=256 ---
    {
        dim3 grid(D_DIM / 64, N_NODES / 64);
        gemm_f32x2_kernel<64, 64, 16, 4, 4, true>
            <<<grid, 256>>>(h, W2, b2, zpre, N_NODES, D_DIM, H_DIM);
    }
    // --- spmm2: z = A @ zpre -> out[0 : N*D] ---
    spmm_csr_kernel<D_DIM, 4><<<N_NODES / 4, 256>>>(zpre, out);

    // --- decoder: out[N*D:] = sigmoid(z z^T), symmetric tiles ---
    {
        const int smem = 2 * 64 * 132 * sizeof(float);   // 67584 B
        cudaFuncSetAttribute(decode_kernel,
                             cudaFuncAttributeMaxDynamicSharedMemorySize, smem);
        int nblk = 64 * 65 / 2;                          // 2080 triangle tiles
        decode_kernel<<<nblk, 256, smem>>>(out, out + (size_t)N_NODES * D_DIM);
    }
}

// round 3
// speedup vs baseline: 1.3612x; 1.2224x over previous
#include <cuda_runtime.h>
#include <cuda_bf16.h>

#define N_NODES 8192
#define F_INP   512
#define H_DIM   256
#define D_DIM   64
#define N_EDGES 262144

typedef unsigned long long ull;

// ---------------- device scratch ---------------------------------------------
__device__ float g_hpre[N_NODES * H_DIM];
__device__ float g_h   [N_NODES * H_DIM];
__device__ float g_zpre[N_NODES * D_DIM];
__device__ int   g_cnt   [N_NODES];        // zero-init at load; re-zeroed by scatter
__device__ int   g_rowptr[N_NODES + 1];
__device__ int   g_fill  [N_NODES];
__device__ int   g_ecol  [N_EDGES];
__device__ float g_eval  [N_EDGES];

// ---------------- packed f32x2 helpers ---------------------------------------
__device__ __forceinline__ void ffma2(ull& acc, ull a, ull b) {
    asm("fma.rn.f32x2 %0, %1, %2, %0;" : "+l"(acc) : "l"(a), "l"(b));
}
__device__ __forceinline__ void unpack2(ull v, float& lo, float& hi) {
    asm("mov.b64 {%0, %1}, %2;" : "=f"(lo), "=f"(hi) : "l"(v));
}

// ============================ CSR build =======================================
__global__ void count_kernel(const int* __restrict__ rows) {
    int e = blockIdx.x * blockDim.x + threadIdx.x;
    if (e < N_EDGES) atomicAdd(&g_cnt[rows[e]], 1);
}

__global__ void scan_kernel() {
    __shared__ int sm[1024];
    int tid  = threadIdx.x;
    int base = tid * 8;
    int v[8], pre[8];
    int s = 0;
    #pragma unroll
    for (int i = 0; i < 8; i++) { v[i] = g_cnt[base + i]; pre[i] = s; s += v[i]; }
    sm[tid] = s;
    __syncthreads();
    for (int off = 1; off < 1024; off <<= 1) {
        int t = (tid >= off) ? sm[tid - off] : 0;
        __syncthreads();
        sm[tid] += t;
        __syncthreads();
    }
    int excl = sm[tid] - s;
    #pragma unroll
    for (int i = 0; i < 8; i++) {
        int p = excl + pre[i];
        g_rowptr[base + i] = p;
        g_fill[base + i]   = p;
    }
    if (tid == 1023) g_rowptr[N_NODES] = sm[1023];
}

// scatter + re-zero g_cnt for the next replay (g_cnt is consumed by scan already)
__global__ void scatter_kernel(const int* __restrict__ rows,
                               const int* __restrict__ cols,
                               const float* __restrict__ vals) {
    int e = blockIdx.x * blockDim.x + threadIdx.x;
    if (e < N_EDGES) {
        int pos = atomicAdd(&g_fill[rows[e]], 1);
        g_ecol[pos] = cols[e];
        g_eval[pos] = vals[e];
    }
    if (e < N_NODES) g_cnt[e] = 0;
}

// ============================ GEMM (dup-A f32x2, double buffered) =============
// C[M,Nc] = op(A) @ B + bias.  256 threads, TM x TN per thread.
template <int BM, int BN, int BK, int TM, int TN, bool RELU_A>
__global__ void __launch_bounds__(256)
gemm_db_kernel(const float* __restrict__ A, const float* __restrict__ B,
               const float* __restrict__ bias, float* __restrict__ C,
               int M, int Nc, int K) {
    constexpr int SB = BN + 4;
    constexpr int AV = BM * BK / (4 * 256);   // float4 A-loads per thread
    constexpr int BV = BK * BN / (4 * 256);   // float4 B-loads per thread
    static_assert(AV >= 1 && BV >= 1, "tile too small");

    __shared__ float2 As[2][BK * BM];         // duplicated pairs: As[k*BM + r] = (v,v)
    __shared__ float  Bs[2][BK * SB];

    const int row0 = blockIdx.y * BM;
    const int col0 = blockIdx.x * BN;
    const int tid  = threadIdx.x;
    const int tx   = tid % (BN / TN);
    const int ty   = tid / (BN / TN);

    float4 areg[AV], breg[BV];

    auto ldg_tile = [&](int k0) {
        #pragma unroll
        for (int v = 0; v < AV; v++) {
            int q = tid + v * 256;
            int r = q / (BK / 4), kq = q % (BK / 4);
            float4 t = *(const float4*)&A[(size_t)(row0 + r) * K + k0 + kq * 4];
            if (RELU_A) {
                t.x = fmaxf(t.x, 0.f); t.y = fmaxf(t.y, 0.f);
                t.z = fmaxf(t.z, 0.f); t.w = fmaxf(t.w, 0.f);
            }
            areg[v] = t;
        }
        #pragma unroll
        for (int v = 0; v < BV; v++) {
            int q = tid + v * 256;
            int k = q / (BN / 4), cq = q % (BN / 4);
            breg[v] = *(const float4*)&B[(size_t)(k0 + k) * Nc + col0 + cq * 4];
        }
    };
    auto sts_tile = [&](int buf) {
        #pragma unroll
        for (int v = 0; v < AV; v++) {
            int q = tid + v * 256;
            int r = q / (BK / 4), kq = q % (BK / 4);
            As[buf][(kq * 4 + 0) * BM + r] = make_float2(areg[v].x, areg[v].x);
            As[buf][(kq * 4 + 1) * BM + r] = make_float2(areg[v].y, areg[v].y);
            As[buf][(kq * 4 + 2) * BM + r] = make_float2(areg[v].z, areg[v].z);
            As[buf][(kq * 4 + 3) * BM + r] = make_float2(areg[v].w, areg[v].w);
        }
        #pragma unroll
        for (int v = 0; v < BV; v++) {
            int q = tid + v * 256;
            int k = q / (BN / 4), cq = q % (BN / 4);
            *(float4*)&Bs[buf][k * SB + cq * 4] = breg[v];
        }
    };

    ull acc[TM][TN / 2];
    #pragma unroll
    for (int i = 0; i < TM; i++)
        #pragma unroll
        for (int j = 0; j < TN / 2; j++) acc[i][j] = 0ULL;

    ldg_tile(0);
    sts_tile(0);
    __syncthreads();

    const int T = K / BK;
    for (int t = 0; t < T; t++) {
        if (t + 1 < T) ldg_tile((t + 1) * BK);
        const int buf = t & 1;
        #pragma unroll
        for (int kk = 0; kk < BK; kk++) {
            ull a[TM];
            #pragma unroll
            for (int i = 0; i < TM; i += 2) {
                ulonglong2 p = *(const ulonglong2*)&As[buf][kk * BM + ty * TM + i];
                a[i] = p.x; a[i + 1] = p.y;
            }
            ull b[TN / 2];
            #pragma unroll
            for (int j = 0; j < TN; j += 4) {
                ulonglong2 p = *(const ulonglong2*)&Bs[buf][kk * SB + tx * TN + j];
                b[j / 2] = p.x; b[j / 2 + 1] = p.y;
            }
            #pragma unroll
            for (int i = 0; i < TM; i++)
                #pragma unroll
                for (int j = 0; j < TN / 2; j++)
                    ffma2(acc[i][j], a[i], b[j]);
        }
        if (t + 1 < T) {
            __syncthreads();
            sts_tile((t + 1) & 1);
            __syncthreads();
        }
    }

    #pragma unroll
    for (int i = 0; i < TM; i++) {
        size_t row = (size_t)(row0 + ty * TM + i);
        #pragma unroll
        for (int j = 0; j < TN / 2; j++) {
            float lo, hi;
            unpack2(acc[i][j], lo, hi);
            int c = col0 + tx * TN + j * 2;
            float2 o = make_float2(lo + __ldg(&bias[c]), hi + __ldg(&bias[c + 1]));
            *(float2*)&C[row * Nc + c] = o;
        }
    }
}

// ============================ CSR SpMM ========================================
template <int F, int ROWS_PER_BLK>
__global__ void spmm_csr_kernel(const float* __restrict__ in,
                                float* __restrict__ out) {
    int sub = threadIdx.x / F;
    int f   = threadIdx.x % F;
    int row = blockIdx.x * ROWS_PER_BLK + sub;
    int s = g_rowptr[row];
    int e = g_rowptr[row + 1];
    float acc = 0.f;
    int j = s;
    for (; j + 4 <= e; j += 4) {
        int   c0 = g_ecol[j],     c1 = g_ecol[j + 1];
        int   c2 = g_ecol[j + 2], c3 = g_ecol[j + 3];
        float v0 = g_eval[j],     v1 = g_eval[j + 1];
        float v2 = g_eval[j + 2], v3 = g_eval[j + 3];
        float x0 = __ldg(&in[(size_t)c0 * F + f]);
        float x1 = __ldg(&in[(size_t)c1 * F + f]);
        float x2 = __ldg(&in[(size_t)c2 * F + f]);
        float x3 = __ldg(&in[(size_t)c3 * F + f]);
        acc = fmaf(v0, x0, acc); acc = fmaf(v1, x1, acc);
        acc = fmaf(v2, x2, acc); acc = fmaf(v3, x3, acc);
    }
    for (; j < e; j++)
        acc = fmaf(g_eval[j], __ldg(&in[(size_t)g_ecol[j] * F + f]), acc);
    out[(size_t)row * F + f] = acc;
}

// ============================ Decoder =========================================
// sigmoid(z z^T) upper-triangle 128x128 tiles + mirror. dup-A f32x2 inner loop.
__global__ void __launch_bounds__(256)
decode_kernel(const float* __restrict__ z, float* __restrict__ out) {
    extern __shared__ char smraw[];
    float2* zi = (float2*)smraw;                     // [64][128] dup pairs (64KB)
    float*  zj = (float*)(smraw + 64 * 128 * 8);     // [64][132]          (33KB)

    int t = blockIdx.x;
    int bi = 0, rem = t;
    while (rem >= 64 - bi) { rem -= 64 - bi; bi++; }
    int bj = bi + rem;
    const int i0 = bi * 128, j0 = bj * 128;
    const int tid = threadIdx.x;

    for (int q = tid; q < 128 * 16; q += 256) {
        int r = q >> 4, c4 = q & 15;
        float4 a = *(const float4*)&z[(size_t)(i0 + r) * 64 + c4 * 4];
        zi[(c4 * 4 + 0) * 128 + r] = make_float2(a.x, a.x);
        zi[(c4 * 4 + 1) * 128 + r] = make_float2(a.y, a.y);
        zi[(c4 * 4 + 2) * 128 + r] = make_float2(a.z, a.z);
        zi[(c4 * 4 + 3) * 128 + r] = make_float2(a.w, a.w);
        float4 b = *(const float4*)&z[(size_t)(j0 + r) * 64 + c4 * 4];
        zj[(c4 * 4 + 0) * 132 + r] = b.x;
        zj[(c4 * 4 + 1) * 132 + r] = b.y;
        zj[(c4 * 4 + 2) * 132 + r] = b.z;
        zj[(c4 * 4 + 3) * 132 + r] = b.w;
    }
    __syncthreads();

    const int tx = tid & 15, ty = tid >> 4;
    ull acc[8][4];
    #pragma unroll
    for (int i = 0; i < 8; i++)
        #pragma unroll
        for (int j = 0; j < 4; j++) acc[i][j] = 0ULL;

    #pragma unroll 4
    for (int k = 0; k < 64; k++) {
        ull a[8];
        #pragma unroll
        for (int i = 0; i < 8; i += 2) {
            ulonglong2 p = *(const ulonglong2*)&zi[k * 128 + ty * 8 + i];
            a[i] = p.x; a[i + 1] = p.y;
        }
        ull b[4];
        {
            ulonglong2 p0 = *(const ulonglong2*)&zj[k * 132 + tx * 8];
            ulonglong2 p1 = *(const ulonglong2*)&zj[k * 132 + tx * 8 + 4];
            b[0] = p0.x; b[1] = p0.y; b[2] = p1.x; b[3] = p1.y;
        }
        #pragma unroll
        for (int i = 0; i < 8; i++)
            #pragma unroll
            for (int j = 0; j < 4; j++)
                ffma2(acc[i][j], a[i], b[j]);
    }

    float sig[8][8];
    #pragma unroll
    for (int i = 0; i < 8; i++)
        #pragma unroll
        for (int j = 0; j < 4; j++) {
            float lo, hi;
            unpack2(acc[i][j], lo, hi);
            sig[i][j * 2]     = 1.f / (1.f + __expf(-lo));
            sig[i][j * 2 + 1] = 1.f / (1.f + __expf(-hi));
        }

    #pragma unroll
    for (int i = 0; i < 8; i++) {
        size_t row = (size_t)(i0 + ty * 8 + i);
        float4 o0 = make_float4(sig[i][0], sig[i][1], sig[i][2], sig[i][3]);
        float4 o1 = make_float4(sig[i][4], sig[i][5], sig[i][6], sig[i][7]);
        *(float4*)&out[row * N_NODES + j0 + tx * 8]     = o0;
        *(float4*)&out[row * N_NODES + j0 + tx * 8 + 4] = o1;
    }

    if (bi != bj) {
        __syncthreads();                 // done reading zi/zj
        float* stg = (float*)smraw;      // [128][129]
        #pragma unroll
        for (int i = 0; i < 8; i++) {
            int r = ty * 8 + i;
            #pragma unroll
            for (int j = 0; j < 8; j++)
                stg[r * 129 + tx * 8 + j] = sig[i][j];
        }
        __syncthreads();
        for (int idx = tid; idx < 128 * 128; idx += 256) {
            int c = idx >> 7;
            int r = idx & 127;
            out[(size_t)(j0 + c) * N_NODES + i0 + r] = stg[r * 129 + c];
        }
    }
}

// ============================ launch ==========================================
extern "C" void kernel_launch(void* const* d_in, const int* in_sizes, int n_in,
                              void* d_out, int out_size) {
    const float* x    = (const float*)d_in[0];
    const int*   rows = (const int*)  d_in[1];
    const int*   cols = (const int*)  d_in[2];
    const float* vals = (const float*)d_in[3];
    const float* W1   = (const float*)d_in[4];
    const float* b1   = (const float*)d_in[5];
    const float* W2   = (const float*)d_in[6];
    const float* b2   = (const float*)d_in[7];
    float* out = (float*)d_out;

    float *hpre, *h, *zpre;
    cudaGetSymbolAddress((void**)&hpre, g_hpre);
    cudaGetSymbolAddress((void**)&h,    g_h);
    cudaGetSymbolAddress((void**)&zpre, g_zpre);

    // 1-3: CSR build (g_cnt zeroed by previous scatter / zero-init)
    count_kernel<<<N_EDGES / 256, 256>>>(rows);
    scan_kernel<<<1, 1024>>>();
    scatter_kernel<<<N_EDGES / 256, 256>>>(rows, cols, vals);

    // 4: layer 1 GEMM (profiled launch): hpre = x @ W1 + b1, [8192,256] K=512
    {
        dim3 grid(H_DIM / 64, N_NODES / 128);   // 4 x 64 = 256 blocks
        gemm_db_kernel<128, 64, 16, 8, 4, false>
            <<<grid, 256>>>(x, W1, b1, hpre, N_NODES, H_DIM, F_INP);
    }
    // 5: spmm1: h = A @ hpre
    spmm_csr_kernel<H_DIM, 1><<<N_NODES, 256>>>(hpre, h);

    // 6: layer 2 GEMM: zpre = relu(h) @ W2 + b2, [8192,64] K=256
    {
        dim3 grid(D_DIM / 64, N_NODES / 64);    // 1 x 128 = 128 blocks
        gemm_db_kernel<64, 64, 16, 4, 4, true>
            <<<grid, 256>>>(h, W2, b2, zpre, N_NODES, D_DIM, H_DIM);
    }
    // 7: spmm2: z = A @ zpre -> out[0 : N*D]
    spmm_csr_kernel<D_DIM, 4><<<N_NODES / 4, 256>>>(zpre, out);

    // 8: decoder
    {
        const int smem = 64 * 128 * 8 + 64 * 132 * 4;   // 99328 B
        cudaFuncSetAttribute(decode_kernel,
                             cudaFuncAttributeMaxDynamicSharedMemorySize, smem);
        int nblk = 64 * 65 / 2;
        decode_kernel<<<nblk, 256, smem>>>(out, out + (size_t)N_NODES * D_DIM);
    }
}

// round 4
// speedup vs baseline: 1.7614x; 1.2940x over previous
#include <cuda_runtime.h>
#include <cuda_bf16.h>

#define N_NODES 8192
#define F_INP   512
#define H_DIM   256
#define D_DIM   64
#define N_EDGES 262144

typedef unsigned long long ull;

// ---------------- device scratch ---------------------------------------------
__device__ float g_hpre[N_NODES * H_DIM];
__device__ float g_h   [N_NODES * H_DIM];
__device__ float g_zpre[N_NODES * D_DIM];
__device__ int   g_cnt   [N_NODES];        // zero-init at load; re-zeroed by scatter
__device__ int   g_rowptr[N_NODES + 1];
__device__ int   g_fill  [N_NODES];
__device__ int   g_ecol  [N_EDGES];
__device__ float g_eval  [N_EDGES];

// ---------------- packed f32x2 helpers ---------------------------------------
__device__ __forceinline__ void ffma2(ull& acc, ull a, ull b) {
    asm("fma.rn.f32x2 %0, %1, %2, %0;" : "+l"(acc) : "l"(a), "l"(b));
}
__device__ __forceinline__ ull pack2(float v) {
    ull r;
    asm("mov.b64 %0, {%1, %1};" : "=l"(r) : "f"(v));
    return r;
}
__device__ __forceinline__ void unpack2(ull v, float& lo, float& hi) {
    asm("mov.b64 {%0, %1}, %2;" : "=f"(lo), "=f"(hi) : "l"(v));
}

// ============================ CSR build =======================================
__global__ void count_kernel(const int* __restrict__ rows) {
    int e = blockIdx.x * blockDim.x + threadIdx.x;
    if (e < N_EDGES) atomicAdd(&g_cnt[rows[e]], 1);
}

__global__ void scan_kernel() {
    __shared__ int sm[1024];
    int tid  = threadIdx.x;
    int base = tid * 8;
    int v[8], pre[8];
    int s = 0;
    #pragma unroll
    for (int i = 0; i < 8; i++) { v[i] = g_cnt[base + i]; pre[i] = s; s += v[i]; }
    sm[tid] = s;
    __syncthreads();
    for (int off = 1; off < 1024; off <<= 1) {
        int t = (tid >= off) ? sm[tid - off] : 0;
        __syncthreads();
        sm[tid] += t;
        __syncthreads();
    }
    int excl = sm[tid] - s;
    #pragma unroll
    for (int i = 0; i < 8; i++) {
        int p = excl + pre[i];
        g_rowptr[base + i] = p;
        g_fill[base + i]   = p;
    }
    if (tid == 1023) g_rowptr[N_NODES] = sm[1023];
}

__global__ void scatter_kernel(const int* __restrict__ rows,
                               const int* __restrict__ cols,
                               const float* __restrict__ vals) {
    int e = blockIdx.x * blockDim.x + threadIdx.x;
    if (e < N_EDGES) {
        int pos = atomicAdd(&g_fill[rows[e]], 1);
        g_ecol[pos] = cols[e];
        g_eval[pos] = vals[e];
    }
    if (e < N_NODES) g_cnt[e] = 0;   // re-zero for next replay
}

// ============================ GEMM (non-dup smem, reg-dup f32x2) ==============
// C[M,Nc] = op(A) @ B + bias.  NT threads, TM x TN per thread.
template <int BM, int BN, int BK, int TM, int TN, int NT, bool RELU_A>
__global__ void __launch_bounds__(NT)
gemm_db_kernel(const float* __restrict__ A, const float* __restrict__ B,
               const float* __restrict__ bias, float* __restrict__ C,
               int M, int Nc, int K) {
    constexpr int SA = BM + 4;
    constexpr int SB = BN + 4;
    constexpr int AV = BM * BK / (4 * NT);
    constexpr int BV = BK * BN / (4 * NT);
    static_assert(AV >= 1 && BV >= 1, "tile too small");
    static_assert((BM / TM) * (BN / TN) == NT, "thread mapping");

    __shared__ float As[2][BK * SA];   // transposed: As[k][r]
    __shared__ float Bs[2][BK * SB];   // Bs[k][c]

    const int row0 = blockIdx.y * BM;
    const int col0 = blockIdx.x * BN;
    const int tid  = threadIdx.x;
    const int tx   = tid % (BN / TN);
    const int ty   = tid / (BN / TN);

    float4 areg[AV], breg[BV];

    auto ldg_tile = [&](int k0) {
        #pragma unroll
        for (int v = 0; v < AV; v++) {
            int q = tid + v * NT;
            int r = q / (BK / 4), kq = q % (BK / 4);
            float4 t = *(const float4*)&A[(size_t)(row0 + r) * K + k0 + kq * 4];
            if (RELU_A) {
                t.x = fmaxf(t.x, 0.f); t.y = fmaxf(t.y, 0.f);
                t.z = fmaxf(t.z, 0.f); t.w = fmaxf(t.w, 0.f);
            }
            areg[v] = t;
        }
        #pragma unroll
        for (int v = 0; v < BV; v++) {
            int q = tid + v * NT;
            int k = q / (BN / 4), cq = q % (BN / 4);
            breg[v] = *(const float4*)&B[(size_t)(k0 + k) * Nc + col0 + cq * 4];
        }
    };
    auto sts_tile = [&](int buf) {
        #pragma unroll
        for (int v = 0; v < AV; v++) {
            int q = tid + v * NT;
            int r = q / (BK / 4), kq = q % (BK / 4);
            As[buf][(kq * 4 + 0) * SA + r] = areg[v].x;
            As[buf][(kq * 4 + 1) * SA + r] = areg[v].y;
            As[buf][(kq * 4 + 2) * SA + r] = areg[v].z;
            As[buf][(kq * 4 + 3) * SA + r] = areg[v].w;
        }
        #pragma unroll
        for (int v = 0; v < BV; v++) {
            int q = tid + v * NT;
            int k = q / (BN / 4), cq = q % (BN / 4);
            *(float4*)&Bs[buf][k * SB + cq * 4] = breg[v];
        }
    };

    ull acc[TM][TN / 2];
    #pragma unroll
    for (int i = 0; i < TM; i++)
        #pragma unroll
        for (int j = 0; j < TN / 2; j++) acc[i][j] = 0ULL;

    ldg_tile(0);
    sts_tile(0);
    __syncthreads();

    const int T = K / BK;
    for (int t = 0; t < T; t++) {
        if (t + 1 < T) ldg_tile((t + 1) * BK);
        const int buf = t & 1;
        #pragma unroll
        for (int kk = 0; kk < BK; kk++) {
            float a_s[TM];
            #pragma unroll
            for (int i = 0; i < TM; i += 4) {
                float4 av = *(const float4*)&As[buf][kk * SA + ty * TM + i];
                a_s[i] = av.x; a_s[i + 1] = av.y; a_s[i + 2] = av.z; a_s[i + 3] = av.w;
            }
            ull b[TN / 2];
            #pragma unroll
            for (int j = 0; j < TN; j += 4) {
                float4 bv = *(const float4*)&Bs[buf][kk * SB + tx * TN + j];
                b[j / 2]     = pack2(bv.x), ((float2*)&b[j / 2])->y     = bv.y;
                b[j / 2 + 1] = pack2(bv.z), ((float2*)&b[j / 2 + 1])->y = bv.w;
            }
            #pragma unroll
            for (int i = 0; i < TM; i++) {
                ull av2 = pack2(a_s[i]);
                #pragma unroll
                for (int j = 0; j < TN / 2; j++)
                    ffma2(acc[i][j], av2, b[j]);
            }
        }
        if (t + 1 < T) {
            sts_tile((t + 1) & 1);
            __syncthreads();
        }
    }

    #pragma unroll
    for (int i = 0; i < TM; i++) {
        size_t row = (size_t)(row0 + ty * TM + i);
        #pragma unroll
        for (int j = 0; j < TN / 2; j++) {
            float lo, hi;
            unpack2(acc[i][j], lo, hi);
            int c = col0 + tx * TN + j * 2;
            float2 o = make_float2(lo + __ldg(&bias[c]), hi + __ldg(&bias[c + 1]));
            *(float2*)&C[row * Nc + c] = o;
        }
    }
}

// ============================ CSR SpMM (float4 lanes) =========================
// TPR = F/4 threads per row; NT threads per block.
template <int F, int NT>
__global__ void __launch_bounds__(NT)
spmm_csr_kernel(const float* __restrict__ in, float* __restrict__ out) {
    constexpr int TPR = F / 4;
    constexpr int RPB = NT / TPR;
    const int sub = threadIdx.x / TPR;
    const int f4  = threadIdx.x % TPR;
    const int row = blockIdx.x * RPB + sub;
    const float4* in4 = (const float4*)in;

    int s = g_rowptr[row];
    int e = g_rowptr[row + 1];
    float4 acc = make_float4(0.f, 0.f, 0.f, 0.f);
    int j = s;
    for (; j + 4 <= e; j += 4) {
        int   c0 = g_ecol[j],     c1 = g_ecol[j + 1];
        int   c2 = g_ecol[j + 2], c3 = g_ecol[j + 3];
        float v0 = g_eval[j],     v1 = g_eval[j + 1];
        float v2 = g_eval[j + 2], v3 = g_eval[j + 3];
        float4 x0 = __ldg(&in4[(size_t)c0 * TPR + f4]);
        float4 x1 = __ldg(&in4[(size_t)c1 * TPR + f4]);
        float4 x2 = __ldg(&in4[(size_t)c2 * TPR + f4]);
        float4 x3 = __ldg(&in4[(size_t)c3 * TPR + f4]);
        acc.x = fmaf(v0, x0.x, acc.x); acc.y = fmaf(v0, x0.y, acc.y);
        acc.z = fmaf(v0, x0.z, acc.z); acc.w = fmaf(v0, x0.w, acc.w);
        acc.x = fmaf(v1, x1.x, acc.x); acc.y = fmaf(v1, x1.y, acc.y);
        acc.z = fmaf(v1, x1.z, acc.z); acc.w = fmaf(v1, x1.w, acc.w);
        acc.x = fmaf(v2, x2.x, acc.x); acc.y = fmaf(v2, x2.y, acc.y);
        acc.z = fmaf(v2, x2.z, acc.z); acc.w = fmaf(v2, x2.w, acc.w);
        acc.x = fmaf(v3, x3.x, acc.x); acc.y = fmaf(v3, x3.y, acc.y);
        acc.z = fmaf(v3, x3.z, acc.z); acc.w = fmaf(v3, x3.w, acc.w);
    }
    for (; j < e; j++) {
        float v = g_eval[j];
        float4 x = __ldg(&in4[(size_t)g_ecol[j] * TPR + f4]);
        acc.x = fmaf(v, x.x, acc.x); acc.y = fmaf(v, x.y, acc.y);
        acc.z = fmaf(v, x.z, acc.z); acc.w = fmaf(v, x.w, acc.w);
    }
    ((float4*)out)[(size_t)row * TPR + f4] = acc;
}

// ============================ Decoder =========================================
// sigmoid(z z^T) upper-triangle 128x128 tiles + mirror. Non-dup smem, reg-dup.
__global__ void __launch_bounds__(256)
decode_kernel(const float* __restrict__ z, float* __restrict__ out) {
    extern __shared__ float sm[];
    float* zi = sm;                  // [64][132]
    float* zj = sm + 64 * 132;       // [64][132]

    int t = blockIdx.x;
    int bi = 0, rem = t;
    while (rem >= 64 - bi) { rem -= 64 - bi; bi++; }
    int bj = bi + rem;
    const int i0 = bi * 128, j0 = bj * 128;
    const int tid = threadIdx.x;

    for (int q = tid; q < 128 * 16; q += 256) {
        int r = q >> 4, c4 = q & 15;
        float4 a = *(const float4*)&z[(size_t)(i0 + r) * 64 + c4 * 4];
        zi[(c4 * 4 + 0) * 132 + r] = a.x;
        zi[(c4 * 4 + 1) * 132 + r] = a.y;
        zi[(c4 * 4 + 2) * 132 + r] = a.z;
        zi[(c4 * 4 + 3) * 132 + r] = a.w;
        float4 b = *(const float4*)&z[(size_t)(j0 + r) * 64 + c4 * 4];
        zj[(c4 * 4 + 0) * 132 + r] = b.x;
        zj[(c4 * 4 + 1) * 132 + r] = b.y;
        zj[(c4 * 4 + 2) * 132 + r] = b.z;
        zj[(c4 * 4 + 3) * 132 + r] = b.w;
    }
    __syncthreads();

    const int tx = tid & 15, ty = tid >> 4;
    ull acc[8][4];
    #pragma unroll
    for (int i = 0; i < 8; i++)
        #pragma unroll
        for (int j = 0; j < 4; j++) acc[i][j] = 0ULL;

    #pragma unroll 4
    for (int k = 0; k < 64; k++) {
        float4 a0 = *(const float4*)&zi[k * 132 + ty * 8];
        float4 a1 = *(const float4*)&zi[k * 132 + ty * 8 + 4];
        float4 b0 = *(const float4*)&zj[k * 132 + tx * 8];
        float4 b1 = *(const float4*)&zj[k * 132 + tx * 8 + 4];
        float a_s[8] = {a0.x, a0.y, a0.z, a0.w, a1.x, a1.y, a1.z, a1.w};
        ull b[4];
        b[0] = pack2(b0.x); ((float2*)&b[0])->y = b0.y;
        b[1] = pack2(b0.z); ((float2*)&b[1])->y = b0.w;
        b[2] = pack2(b1.x); ((float2*)&b[2])->y = b1.y;
        b[3] = pack2(b1.z); ((float2*)&b[3])->y = b1.w;
        #pragma unroll
        for (int i = 0; i < 8; i++) {
            ull av = pack2(a_s[i]);
            #pragma unroll
            for (int j = 0; j < 4; j++)
                ffma2(acc[i][j], av, b[j]);
        }
    }

    float sig[8][8];
    #pragma unroll
    for (int i = 0; i < 8; i++)
        #pragma unroll
        for (int j = 0; j < 4; j++) {
            float lo, hi;
            unpack2(acc[i][j], lo, hi);
            sig[i][j * 2]     = 1.f / (1.f + __expf(-lo));
            sig[i][j * 2 + 1] = 1.f / (1.f + __expf(-hi));
        }

    #pragma unroll
    for (int i = 0; i < 8; i++) {
        size_t row = (size_t)(i0 + ty * 8 + i);
        float4 o0 = make_float4(sig[i][0], sig[i][1], sig[i][2], sig[i][3]);
        float4 o1 = make_float4(sig[i][4], sig[i][5], sig[i][6], sig[i][7]);
        *(float4*)&out[row * N_NODES + j0 + tx * 8]     = o0;
        *(float4*)&out[row * N_NODES + j0 + tx * 8 + 4] = o1;
    }

    if (bi != bj) {
        __syncthreads();                 // done reading zi/zj
        float* stg = sm;                 // [128][129] = 66048 B, fits in 67.5 KB
        #pragma unroll
        for (int i = 0; i < 8; i++) {
            int r = ty * 8 + i;
            #pragma unroll
            for (int j = 0; j < 8; j++)
                stg[r * 129 + tx * 8 + j] = sig[i][j];
        }
        __syncthreads();
        for (int idx = tid; idx < 128 * 128; idx += 256) {
            int c = idx >> 7;
            int r = idx & 127;
            out[(size_t)(j0 + c) * N_NODES + i0 + r] = stg[r * 129 + c];
        }
    }
}

// ============================ launch ==========================================
extern "C" void kernel_launch(void* const* d_in, const int* in_sizes, int n_in,
                              void* d_out, int out_size) {
    const float* x    = (const float*)d_in[0];
    const int*   rows = (const int*)  d_in[1];
    const int*   cols = (const int*)  d_in[2];
    const float* vals = (const float*)d_in[3];
    const float* W1   = (const float*)d_in[4];
    const float* b1   = (const float*)d_in[5];
    const float* W2   = (const float*)d_in[6];
    const float* b2   = (const float*)d_in[7];
    float* out = (float*)d_out;

    float *hpre, *h, *zpre;
    cudaGetSymbolAddress((void**)&hpre, g_hpre);
    cudaGetSymbolAddress((void**)&h,    g_h);
    cudaGetSymbolAddress((void**)&zpre, g_zpre);

    // 1-3: CSR build
    count_kernel<<<N_EDGES / 256, 256>>>(rows);
    scan_kernel<<<1, 1024>>>();
    scatter_kernel<<<N_EDGES / 256, 256>>>(rows, cols, vals);

    // 4: layer 1 GEMM (profiled launch): hpre = x @ W1 + b1, [8192,256] K=512
    {
        dim3 grid(H_DIM / 128, N_NODES / 128);   // 2 x 64 = 128 blocks
        gemm_db_kernel<128, 128, 16, 8, 8, 256, false>
            <<<grid, 256>>>(x, W1, b1, hpre, N_NODES, H_DIM, F_INP);
    }
    // 5: spmm1: h = A @ hpre
    spmm_csr_kernel<H_DIM, 256><<<N_NODES / 4, 256>>>(hpre, h);

    // 6: layer 2 GEMM: zpre = relu(h) @ W2 + b2, [8192,64] K=256
    {
        dim3 grid(D_DIM / 64, N_NODES / 64);     // 1 x 128 = 128 blocks
        gemm_db_kernel<64, 64, 16, 8, 4, 128, true>
            <<<grid, 128>>>(h, W2, b2, zpre, N_NODES, D_DIM, H_DIM);
    }
    // 7: spmm2: z = A @ zpre -> out[0 : N*D]
    spmm_csr_kernel<D_DIM, 256><<<N_NODES / 16, 256>>>(zpre, out);

    // 8: decoder
    {
        const int smem = 2 * 64 * 132 * sizeof(float);   // 67584 B
        cudaFuncSetAttribute(decode_kernel,
                             cudaFuncAttributeMaxDynamicSharedMemorySize, smem);
        int nblk = 64 * 65 / 2;
        decode_kernel<<<nblk, 256, smem>>>(out, out + (size_t)N_NODES * D_DIM);
    }
}